// round 7
// baseline (speedup 1.0000x reference)
#include <cuda_runtime.h>
#include <cuda_bf16.h>
#include <cuda_fp16.h>
#include <math.h>
#include <stddef.h>
#include <stdint.h>

#define N_NODES 50000
#define N_EDGES 800000
#define IN_FEATS 256
#define HD 256          // NUM_HEADS * OUT_FEATS
#define NUM_HEADS 8
#define OUT_FEATS 32
#define NUM_ET 5
#define DEG_BINS 256    // degree histogram bins (clamped)

// ---------------- scratch (static device globals; no allocation) ----------
__device__ __half g_feat_src[(size_t)N_NODES * HD];         // 25.6 MB (fp16)
__device__ int    g_cnt[(size_t)N_NODES * NUM_ET];          // 1 MB (BSS zero)
__device__ float  g_w[(size_t)N_NODES * NUM_ET * NUM_HEADS];// 8 MB
__device__ int    g_off[N_NODES];
__device__ int    g_deg[N_NODES];
__device__ int    g_cur[N_NODES];
__device__ int    g_order[N_NODES];                          // deg-sorted node ids
__device__ int    g_dhist[DEG_BINS];                         // BSS zero
__device__ int    g_dbase[DEG_BINS];
__device__ int2   g_csr2[N_EDGES];                           // {src|t<<16, e}
__device__ int    g_total;

// =====================================================================
// 1) GEMM: C[M,256](fp16) = A[M,256]*B[256,256]^T, single-pass tf32 MMA.
//    BM=128, BN=128, BK=32, 256 threads, 8 warps (4Mx2N), warp 32x64.
// =====================================================================
__device__ __forceinline__ void mma_tf32(float* c, const uint32_t* a,
                                         uint32_t b0, uint32_t b1) {
    asm volatile(
        "mma.sync.aligned.m16n8k8.row.col.f32.tf32.tf32.f32 "
        "{%0,%1,%2,%3},{%4,%5,%6,%7},{%8,%9},{%0,%1,%2,%3};\n"
        : "+f"(c[0]), "+f"(c[1]), "+f"(c[2]), "+f"(c[3])
        : "r"(a[0]), "r"(a[1]), "r"(a[2]), "r"(a[3]), "r"(b0), "r"(b1));
}

__device__ __forceinline__ float tf32r(float x) {
    float y;
    asm("cvt.rna.tf32.f32 %0, %1;" : "=f"(y) : "f"(x));
    return y;
}

__device__ __forceinline__ void cvt_store4(float* p, float4 v) {
    p[0] = tf32r(v.x);
    p[1] = tf32r(v.y);
    p[2] = tf32r(v.z);
    p[3] = tf32r(v.w);
}

__global__ __launch_bounds__(256) void gemm_tf32_kernel(
    const float* __restrict__ A, const float* __restrict__ B,
    __half* __restrict__ C, int M) {
    __shared__ float As[128][36];
    __shared__ float Bs[128][36];

    const int tid = threadIdx.x;
    const int m0 = blockIdx.x * 128;
    const int n0 = blockIdx.y * 128;
    const int warp = tid >> 5, lane = tid & 31;
    const int wm0 = (warp >> 1) * 32;
    const int wn0 = (warp & 1) * 64;
    const int g = lane >> 2, tg = lane & 3;

    const int row0 = tid >> 3;
    const int ac4 = (tid & 7) * 4;

    float acc[2][8][4];
#pragma unroll
    for (int i = 0; i < 2; i++)
#pragma unroll
        for (int j = 0; j < 8; j++)
#pragma unroll
            for (int q = 0; q < 4; q++) acc[i][j][q] = 0.f;

    float4 pa[4], pb[4];
#pragma unroll
    for (int r = 0; r < 4; r++) {
        int row = row0 + r * 32;
        pa[r] = make_float4(0.f, 0.f, 0.f, 0.f);
        if (m0 + row < M)
            pa[r] = __ldg((const float4*)(A + (size_t)(m0 + row) * 256 + ac4));
        pb[r] = __ldg((const float4*)(B + (size_t)(n0 + row) * 256 + ac4));
    }

#pragma unroll 1
    for (int k0 = 0; k0 < 256; k0 += 32) {
#pragma unroll
        for (int r = 0; r < 4; r++) {
            int row = row0 + r * 32;
            cvt_store4(&As[row][ac4], pa[r]);
            cvt_store4(&Bs[row][ac4], pb[r]);
        }
        __syncthreads();

        if (k0 + 32 < 256) {
            const int kn = k0 + 32;
#pragma unroll
            for (int r = 0; r < 4; r++) {
                int row = row0 + r * 32;
                if (m0 + row < M)
                    pa[r] = __ldg((const float4*)(A + (size_t)(m0 + row) * 256 + kn + ac4));
                pb[r] = __ldg((const float4*)(B + (size_t)(n0 + row) * 256 + kn + ac4));
            }
        }

#pragma unroll
        for (int kf = 0; kf < 4; kf++) {
            const int kk = kf * 8;
            uint32_t a[2][4], b[8][2];
#pragma unroll
            for (int i = 0; i < 2; i++) {
                int r0 = wm0 + i * 16 + g;
                a[i][0] = *(const uint32_t*)&As[r0][kk + tg];
                a[i][1] = *(const uint32_t*)&As[r0 + 8][kk + tg];
                a[i][2] = *(const uint32_t*)&As[r0][kk + tg + 4];
                a[i][3] = *(const uint32_t*)&As[r0 + 8][kk + tg + 4];
            }
#pragma unroll
            for (int j = 0; j < 8; j++) {
                int c0 = wn0 + j * 8 + g;
                b[j][0] = *(const uint32_t*)&Bs[c0][kk + tg];
                b[j][1] = *(const uint32_t*)&Bs[c0][kk + tg + 4];
            }
#pragma unroll
            for (int i = 0; i < 2; i++)
#pragma unroll
                for (int j = 0; j < 8; j++)
                    mma_tf32(acc[i][j], a[i], b[j][0], b[j][1]);
        }
        __syncthreads();
    }

#pragma unroll
    for (int i = 0; i < 2; i++)
#pragma unroll
        for (int j = 0; j < 8; j++) {
            int m_lo = m0 + wm0 + i * 16 + g;
            int col  = n0 + wn0 + j * 8 + tg * 2;
            if (m_lo < M)
                *(__half2*)(C + (size_t)m_lo * 256 + col) =
                    __floats2half2_rn(acc[i][j][0], acc[i][j][1]);
            if (m_lo + 8 < M)
                *(__half2*)(C + (size_t)(m_lo + 8) * 256 + col) =
                    __floats2half2_rn(acc[i][j][2], acc[i][j][3]);
        }
}

// ---------------- 2) histogram, 1 edge/thread (+ clear g_total) -----------
__global__ void count_kernel(const int* __restrict__ dst,
                             const int* __restrict__ ef) {
    int i = blockIdx.x * blockDim.x + threadIdx.x;
    if (i == 0) g_total = 0;
    if (i < N_EDGES)
        atomicAdd(&g_cnt[(size_t)dst[i] * NUM_ET + ef[i]], 1);
}

// ------- 3) fused CSR offsets + softmax + degree histogram ---------------
__global__ void offsets_softmax_kernel(const float* __restrict__ emb) {
    int n = blockIdx.x * blockDim.x + threadIdx.x;
    int lane = threadIdx.x & 31;

    int c[NUM_ET];
    int deg = 0;
    if (n < N_NODES) {
#pragma unroll
        for (int t = 0; t < NUM_ET; t++) {
            c[t] = g_cnt[(size_t)n * NUM_ET + t];
            deg += c[t];
        }
#pragma unroll
        for (int t = 0; t < NUM_ET; t++)
            g_cnt[(size_t)n * NUM_ET + t] = 0;   // restore for next replay
    }
    int incl = deg;
#pragma unroll
    for (int o = 1; o < 32; o <<= 1) {
        int v = __shfl_up_sync(0xffffffffu, incl, o);
        if (lane >= o) incl += v;
    }
    int total = __shfl_sync(0xffffffffu, incl, 31);
    int base = 0;
    if (lane == 0) base = atomicAdd(&g_total, total);
    base = __shfl_sync(0xffffffffu, base, 0);

    if (n < N_NODES) {
        int off = base + incl - deg;
        g_off[n] = off;
        g_cur[n] = off;
        g_deg[n] = deg;
        // degree histogram for counting sort
        int db = deg < DEG_BINS ? deg : (DEG_BINS - 1);
        atomicAdd(&g_dhist[db], 1);

#pragma unroll
        for (int h = 0; h < NUM_HEADS; h++) {
            float ev[NUM_ET];
            float m = -INFINITY;
#pragma unroll
            for (int t = 0; t < NUM_ET; t++) {
                ev[t] = __ldg(emb + t * NUM_HEADS + h);
                if (c[t] > 0) m = fmaxf(m, ev[t]);
            }
            float ex[NUM_ET];
            float denom = 0.f;
#pragma unroll
            for (int t = 0; t < NUM_ET; t++) {
                ex[t] = expf(ev[t] - m);
                denom += (float)c[t] * ex[t];
            }
            float inv = 1.f / denom;   // NaN only for deg==0 nodes (unread)
#pragma unroll
            for (int t = 0; t < NUM_ET; t++)
                g_w[((size_t)n * NUM_ET + t) * NUM_HEADS + h] = ex[t] * inv;
        }
    }
}

// ---- 3b) single-block descending scan of degree histogram (+ re-zero) ----
__global__ void deg_scan_kernel() {
    __shared__ int sh[DEG_BINS];
    int t = threadIdx.x;                 // 256 threads
    int v = g_dhist[t];
    sh[t] = v;
    __syncthreads();
    // exclusive suffix sum: base[d] = sum_{d' > d} hist[d']  (descending order)
    int suf = 0;
    for (int d = t + 1; d < DEG_BINS; d++) suf += sh[d];  // fine for 256 bins
    g_dbase[t] = suf;
    g_dhist[t] = 0;                      // restore for next replay
}

// ---- 3c) scatter node ids into degree-descending order -------------------
__global__ void order_kernel() {
    int n = blockIdx.x * blockDim.x + threadIdx.x;
    if (n >= N_NODES) return;
    int deg = g_deg[n];
    int db = deg < DEG_BINS ? deg : (DEG_BINS - 1);
    int pos = atomicAdd(&g_dbase[db], 1);
    g_order[pos] = n;
}

// ---------------- 4) scatter edges into CSR (slim), 1 edge/thread ---------
__global__ void scatter_csr_kernel(const int* __restrict__ src,
                                   const int* __restrict__ dst,
                                   const int* __restrict__ ef) {
    int e = blockIdx.x * blockDim.x + threadIdx.x;
    if (e >= N_EDGES) return;
    int s = src[e];
    int d = dst[e];
    int t = ef[e];
    int pos = atomicAdd(&g_cur[d], 1);
    g_csr2[pos] = make_int2(s | (t << 16), e);
}

// -------- 5) CSR aggregation + fused attn write, degree-sorted nodes ------
__global__ __launch_bounds__(256) void agg_csr_kernel(float* __restrict__ rst,
                                                      float* __restrict__ attn_out) {
    __shared__ float sw[8][NUM_ET * NUM_HEADS];
    const int warp = threadIdx.x >> 5;
    const int lane = threadIdx.x & 31;
    const int slot = blockIdx.x * 8 + warp;
    if (slot >= N_NODES) return;
    const int d = g_order[slot];          // degree-sorted (descending)

    sw[warp][lane] = g_w[(size_t)d * 40 + lane];
    if (lane < 8) sw[warp][32 + lane] = g_w[(size_t)d * 40 + 32 + lane];
    __syncwarp();

    const int off = g_off[d];
    const int deg = g_deg[d];
    const int h0 = lane >> 2;
    const int sel = lane >> 3;
    const int hl  = lane & 7;
    const uint4* base = (const uint4*)g_feat_src;

    float acc[8];
#pragma unroll
    for (int q = 0; q < 8; q++) acc[q] = 0.f;

    int i = 0;
    for (; i + 8 <= deg; i += 8) {
        int2 qq[8];
        uint4 vv[8];
        float ww[8];
#pragma unroll
        for (int u = 0; u < 8; u++) qq[u] = g_csr2[off + i + u];
#pragma unroll
        for (int u = 0; u < 8; u++)
            vv[u] = __ldg(base + (size_t)(qq[u].x & 0xFFFF) * 32 + lane);
#pragma unroll
        for (int u = 0; u < 8; u++) ww[u] = sw[warp][(qq[u].x >> 16) * 8 + h0];
#pragma unroll
        for (int u = 0; u < 8; u++) {
            const uint32_t* uv = &vv[u].x;
#pragma unroll
            for (int q = 0; q < 4; q++) {
                float2 f = __half22float2(*(const __half2*)&uv[q]);
                acc[q * 2]     += ww[u] * f.x;
                acc[q * 2 + 1] += ww[u] * f.y;
            }
        }
        {
            int2 qa = qq[sel];
            int2 qb = qq[sel + 4];
            attn_out[(size_t)qa.y * NUM_HEADS + hl] = sw[warp][(qa.x >> 16) * 8 + hl];
            attn_out[(size_t)qb.y * NUM_HEADS + hl] = sw[warp][(qb.x >> 16) * 8 + hl];
        }
    }
    for (; i + 4 <= deg; i += 4) {
        int2 qq[4];
        uint4 vv[4];
#pragma unroll
        for (int u = 0; u < 4; u++) qq[u] = g_csr2[off + i + u];
#pragma unroll
        for (int u = 0; u < 4; u++)
            vv[u] = __ldg(base + (size_t)(qq[u].x & 0xFFFF) * 32 + lane);
#pragma unroll
        for (int u = 0; u < 4; u++) {
            float w = sw[warp][(qq[u].x >> 16) * 8 + h0];
            const uint32_t* uv = &vv[u].x;
#pragma unroll
            for (int q = 0; q < 4; q++) {
                float2 f = __half22float2(*(const __half2*)&uv[q]);
                acc[q * 2]     += w * f.x;
                acc[q * 2 + 1] += w * f.y;
            }
        }
        int2 qa = qq[sel];
        attn_out[(size_t)qa.y * NUM_HEADS + hl] = sw[warp][(qa.x >> 16) * 8 + hl];
    }
    for (; i < deg; i++) {
        int2 q0 = g_csr2[off + i];
        uint4 v0 = __ldg(base + (size_t)(q0.x & 0xFFFF) * 32 + lane);
        float w0 = sw[warp][(q0.x >> 16) * 8 + h0];
        const uint32_t* u0 = &v0.x;
#pragma unroll
        for (int q = 0; q < 4; q++) {
            float2 f0 = __half22float2(*(const __half2*)&u0[q]);
            acc[q * 2]     += w0 * f0.x;
            acc[q * 2 + 1] += w0 * f0.y;
        }
        if (lane < 8)
            attn_out[(size_t)q0.y * NUM_HEADS + lane] = sw[warp][(q0.x >> 16) * 8 + lane];
    }

    float4* out = (float4*)(rst + (size_t)d * HD) + lane * 2;
    out[0] = make_float4(acc[0], acc[1], acc[2], acc[3]);
    out[1] = make_float4(acc[4], acc[5], acc[6], acc[7]);
}

// ---------------- launch ---------------------------------------------------
extern "C" void kernel_launch(void* const* d_in, const int* in_sizes, int n_in,
                              void* d_out, int out_size) {
    const float* feat   = (const float*)d_in[0];   // [N, 256]
    const float* fc_w   = (const float*)d_in[1];   // [256, 256]
    const float* emb    = (const float*)d_in[2];   // [5, 8]
    const int*   e_feat = (const int*)d_in[3];     // [E]
    const int*   src    = (const int*)d_in[4];     // [E]
    const int*   dst    = (const int*)d_in[5];     // [E]

    float* out_rst  = (float*)d_out;                           // [N, 8, 32]
    float* out_attn = (float*)d_out + (size_t)N_NODES * HD;    // [E, 8]

    void* fs_ptr = nullptr;
    cudaGetSymbolAddress(&fs_ptr, g_feat_src);

    // 1) GEMM (tensor cores, tf32 single pass)
    {
        dim3 grid((N_NODES + 127) / 128, HD / 128);
        gemm_tf32_kernel<<<grid, 256>>>(feat, fc_w, (__half*)fs_ptr, N_NODES);
    }
    // 2) histogram (+ clears g_total)
    count_kernel<<<(N_EDGES + 255) / 256, 256>>>(dst, e_feat);
    // 3) fused offsets + softmax + degree histogram (+ re-zeroes g_cnt)
    offsets_softmax_kernel<<<(N_NODES + 255) / 256, 256>>>(emb);
    // 3b) degree-bin bases (descending), re-zeroes g_dhist
    deg_scan_kernel<<<1, DEG_BINS>>>();
    // 3c) degree-sorted node order
    order_kernel<<<(N_NODES + 255) / 256, 256>>>();
    // 4) slim scatter to CSR
    scatter_csr_kernel<<<(N_EDGES + 255) / 256, 256>>>(src, dst, e_feat);
    // 5) aggregation + fused attn write (degree-balanced warps)
    agg_csr_kernel<<<(N_NODES + 7) / 8, 256>>>(out_rst, out_attn);
}

// round 8
// speedup vs baseline: 1.0282x; 1.0282x over previous
#include <cuda_runtime.h>
#include <cuda_bf16.h>
#include <cuda_fp16.h>
#include <math.h>
#include <stddef.h>
#include <stdint.h>

#define N_NODES 50000
#define N_EDGES 800000
#define IN_FEATS 256
#define HD 256          // NUM_HEADS * OUT_FEATS
#define NUM_HEADS 8
#define OUT_FEATS 32
#define NUM_ET 5

// ---------------- scratch (static device globals; no allocation) ----------
__device__ __half g_feat_src[(size_t)N_NODES * HD];         // 25.6 MB (fp16)
__device__ int    g_cnt[(size_t)N_NODES * NUM_ET];          // 1 MB (BSS zero)
__device__ float  g_w[(size_t)N_NODES * NUM_ET * NUM_HEADS];// 8 MB
__device__ int    g_off[N_NODES];
__device__ int    g_deg[N_NODES];
__device__ int    g_cur[N_NODES];
__device__ int2   g_csr2[N_EDGES];                          // {src|t<<16, e}
__device__ int    g_total;

// =====================================================================
// 1) GEMM: C[M,256](fp16) = A[M,256]*B[256,256]^T, single-pass tf32 MMA.
//    BM=128, BN=128, BK=32, 256 threads, 8 warps (4Mx2N), warp 32x64.
// =====================================================================
__device__ __forceinline__ void mma_tf32(float* c, const uint32_t* a,
                                         uint32_t b0, uint32_t b1) {
    asm volatile(
        "mma.sync.aligned.m16n8k8.row.col.f32.tf32.tf32.f32 "
        "{%0,%1,%2,%3},{%4,%5,%6,%7},{%8,%9},{%0,%1,%2,%3};\n"
        : "+f"(c[0]), "+f"(c[1]), "+f"(c[2]), "+f"(c[3])
        : "r"(a[0]), "r"(a[1]), "r"(a[2]), "r"(a[3]), "r"(b0), "r"(b1));
}

__device__ __forceinline__ float tf32r(float x) {
    float y;
    asm("cvt.rna.tf32.f32 %0, %1;" : "=f"(y) : "f"(x));
    return y;
}

__device__ __forceinline__ void cvt_store4(float* p, float4 v) {
    p[0] = tf32r(v.x);
    p[1] = tf32r(v.y);
    p[2] = tf32r(v.z);
    p[3] = tf32r(v.w);
}

__global__ __launch_bounds__(256) void gemm_tf32_kernel(
    const float* __restrict__ A, const float* __restrict__ B,
    __half* __restrict__ C, int M) {
    __shared__ float As[128][36];
    __shared__ float Bs[128][36];

    const int tid = threadIdx.x;
    const int m0 = blockIdx.x * 128;
    const int n0 = blockIdx.y * 128;
    const int warp = tid >> 5, lane = tid & 31;
    const int wm0 = (warp >> 1) * 32;
    const int wn0 = (warp & 1) * 64;
    const int g = lane >> 2, tg = lane & 3;

    const int row0 = tid >> 3;
    const int ac4 = (tid & 7) * 4;

    float acc[2][8][4];
#pragma unroll
    for (int i = 0; i < 2; i++)
#pragma unroll
        for (int j = 0; j < 8; j++)
#pragma unroll
            for (int q = 0; q < 4; q++) acc[i][j][q] = 0.f;

    float4 pa[4], pb[4];
#pragma unroll
    for (int r = 0; r < 4; r++) {
        int row = row0 + r * 32;
        pa[r] = make_float4(0.f, 0.f, 0.f, 0.f);
        if (m0 + row < M)
            pa[r] = __ldg((const float4*)(A + (size_t)(m0 + row) * 256 + ac4));
        pb[r] = __ldg((const float4*)(B + (size_t)(n0 + row) * 256 + ac4));
    }

#pragma unroll 1
    for (int k0 = 0; k0 < 256; k0 += 32) {
#pragma unroll
        for (int r = 0; r < 4; r++) {
            int row = row0 + r * 32;
            cvt_store4(&As[row][ac4], pa[r]);
            cvt_store4(&Bs[row][ac4], pb[r]);
        }
        __syncthreads();

        if (k0 + 32 < 256) {
            const int kn = k0 + 32;
#pragma unroll
            for (int r = 0; r < 4; r++) {
                int row = row0 + r * 32;
                if (m0 + row < M)
                    pa[r] = __ldg((const float4*)(A + (size_t)(m0 + row) * 256 + kn + ac4));
                pb[r] = __ldg((const float4*)(B + (size_t)(n0 + row) * 256 + kn + ac4));
            }
        }

#pragma unroll
        for (int kf = 0; kf < 4; kf++) {
            const int kk = kf * 8;
            uint32_t a[2][4], b[8][2];
#pragma unroll
            for (int i = 0; i < 2; i++) {
                int r0 = wm0 + i * 16 + g;
                a[i][0] = *(const uint32_t*)&As[r0][kk + tg];
                a[i][1] = *(const uint32_t*)&As[r0 + 8][kk + tg];
                a[i][2] = *(const uint32_t*)&As[r0][kk + tg + 4];
                a[i][3] = *(const uint32_t*)&As[r0 + 8][kk + tg + 4];
            }
#pragma unroll
            for (int j = 0; j < 8; j++) {
                int c0 = wn0 + j * 8 + g;
                b[j][0] = *(const uint32_t*)&Bs[c0][kk + tg];
                b[j][1] = *(const uint32_t*)&Bs[c0][kk + tg + 4];
            }
#pragma unroll
            for (int i = 0; i < 2; i++)
#pragma unroll
                for (int j = 0; j < 8; j++)
                    mma_tf32(acc[i][j], a[i], b[j][0], b[j][1]);
        }
        __syncthreads();
    }

#pragma unroll
    for (int i = 0; i < 2; i++)
#pragma unroll
        for (int j = 0; j < 8; j++) {
            int m_lo = m0 + wm0 + i * 16 + g;
            int col  = n0 + wn0 + j * 8 + tg * 2;
            if (m_lo < M)
                *(__half2*)(C + (size_t)m_lo * 256 + col) =
                    __floats2half2_rn(acc[i][j][0], acc[i][j][1]);
            if (m_lo + 8 < M)
                *(__half2*)(C + (size_t)(m_lo + 8) * 256 + col) =
                    __floats2half2_rn(acc[i][j][2], acc[i][j][3]);
        }
}

// ---------------- 2) histogram, 1 edge/thread (+ clear g_total) -----------
__global__ void count_kernel(const int* __restrict__ dst,
                             const int* __restrict__ ef) {
    int i = blockIdx.x * blockDim.x + threadIdx.x;
    if (i == 0) g_total = 0;
    if (i < N_EDGES)
        atomicAdd(&g_cnt[(size_t)dst[i] * NUM_ET + ef[i]], 1);
}

// ------- 3) fused CSR offsets + softmax (+ re-zero g_cnt for next run) ----
__global__ void offsets_softmax_kernel(const float* __restrict__ emb) {
    int n = blockIdx.x * blockDim.x + threadIdx.x;
    int lane = threadIdx.x & 31;

    int c[NUM_ET];
    int deg = 0;
    if (n < N_NODES) {
#pragma unroll
        for (int t = 0; t < NUM_ET; t++) {
            c[t] = g_cnt[(size_t)n * NUM_ET + t];
            deg += c[t];
        }
#pragma unroll
        for (int t = 0; t < NUM_ET; t++)
            g_cnt[(size_t)n * NUM_ET + t] = 0;   // restore for next replay
    }
    int incl = deg;
#pragma unroll
    for (int o = 1; o < 32; o <<= 1) {
        int v = __shfl_up_sync(0xffffffffu, incl, o);
        if (lane >= o) incl += v;
    }
    int total = __shfl_sync(0xffffffffu, incl, 31);
    int base = 0;
    if (lane == 0) base = atomicAdd(&g_total, total);
    base = __shfl_sync(0xffffffffu, base, 0);

    if (n < N_NODES) {
        int off = base + incl - deg;
        g_off[n] = off;
        g_cur[n] = off;
        g_deg[n] = deg;

#pragma unroll
        for (int h = 0; h < NUM_HEADS; h++) {
            float ev[NUM_ET];
            float m = -INFINITY;
#pragma unroll
            for (int t = 0; t < NUM_ET; t++) {
                ev[t] = __ldg(emb + t * NUM_HEADS + h);
                if (c[t] > 0) m = fmaxf(m, ev[t]);
            }
            float ex[NUM_ET];
            float denom = 0.f;
#pragma unroll
            for (int t = 0; t < NUM_ET; t++) {
                ex[t] = expf(ev[t] - m);
                denom += (float)c[t] * ex[t];
            }
            float inv = 1.f / denom;   // NaN only for deg==0 nodes (unread)
#pragma unroll
            for (int t = 0; t < NUM_ET; t++)
                g_w[((size_t)n * NUM_ET + t) * NUM_HEADS + h] = ex[t] * inv;
        }
    }
}

// ---------------- 4) scatter edges into CSR (slim), 1 edge/thread ---------
__global__ void scatter_csr_kernel(const int* __restrict__ src,
                                   const int* __restrict__ dst,
                                   const int* __restrict__ ef) {
    int e = blockIdx.x * blockDim.x + threadIdx.x;
    if (e >= N_EDGES) return;
    int s = src[e];
    int d = dst[e];
    int t = ef[e];
    int pos = atomicAdd(&g_cur[d], 1);
    g_csr2[pos] = make_int2(s | (t << 16), e);
}

// -------- 5) CSR aggregation + fused attn write: 2 warps per node ---------
// Block = 256 threads = 8 warps = 4 nodes. Warp pair (2w, 2w+1) covers one
// node; warp half h covers feature cols [h*128, h*128+128). Each lane loads
// uint2 (4 fp16). Even warp also emits attn.
__global__ __launch_bounds__(256) void agg_csr_kernel(float* __restrict__ rst,
                                                      float* __restrict__ attn_out) {
    __shared__ float sw[4][NUM_ET * NUM_HEADS];
    const int warp = threadIdx.x >> 5;
    const int lane = threadIdx.x & 31;
    const int node_slot = warp >> 1;          // 0..3
    const int half = warp & 1;                // 0: cols 0-127, 1: cols 128-255
    const int d = blockIdx.x * 4 + node_slot;

    if (d < N_NODES && half == 0) {
        sw[node_slot][lane] = g_w[(size_t)d * 40 + lane];
        if (lane < 8) sw[node_slot][32 + lane] = g_w[(size_t)d * 40 + 32 + lane];
    }
    __syncthreads();
    if (d >= N_NODES) return;

    const int off = g_off[d];
    const int deg = g_deg[d];
    // lane covers fp16 cols [half*128 + lane*4, +4) -> head:
    const int h0 = half * 4 + (lane >> 3);
    const int sel = lane >> 3;                // attn edge selector (even warp)
    const int hl  = lane & 7;
    const uint2* base = (const uint2*)g_feat_src;   // row = 64 uint2
    const int lcol = half * 32 + lane;              // uint2 index within row
    const float* swn = sw[node_slot];

    float acc[4];
#pragma unroll
    for (int q = 0; q < 4; q++) acc[q] = 0.f;

    int i = 0;
    for (; i + 8 <= deg; i += 8) {
        int2 qq[8];
        uint2 vv[8];
        float ww[8];
#pragma unroll
        for (int u = 0; u < 8; u++) qq[u] = g_csr2[off + i + u];
#pragma unroll
        for (int u = 0; u < 8; u++)
            vv[u] = __ldg(base + (size_t)(qq[u].x & 0xFFFF) * 64 + lcol);
#pragma unroll
        for (int u = 0; u < 8; u++) ww[u] = swn[(qq[u].x >> 16) * 8 + h0];
#pragma unroll
        for (int u = 0; u < 8; u++) {
            float2 f0 = __half22float2(*(const __half2*)&vv[u].x);
            float2 f1 = __half22float2(*(const __half2*)&vv[u].y);
            acc[0] += ww[u] * f0.x;
            acc[1] += ww[u] * f0.y;
            acc[2] += ww[u] * f1.x;
            acc[3] += ww[u] * f1.y;
        }
        if (half == 0) {
            int2 qa = qq[sel];
            int2 qb = qq[sel + 4];
            attn_out[(size_t)qa.y * NUM_HEADS + hl] = swn[(qa.x >> 16) * 8 + hl];
            attn_out[(size_t)qb.y * NUM_HEADS + hl] = swn[(qb.x >> 16) * 8 + hl];
        }
    }
    for (; i + 4 <= deg; i += 4) {
        int2 qq[4];
        uint2 vv[4];
#pragma unroll
        for (int u = 0; u < 4; u++) qq[u] = g_csr2[off + i + u];
#pragma unroll
        for (int u = 0; u < 4; u++)
            vv[u] = __ldg(base + (size_t)(qq[u].x & 0xFFFF) * 64 + lcol);
#pragma unroll
        for (int u = 0; u < 4; u++) {
            float w = swn[(qq[u].x >> 16) * 8 + h0];
            float2 f0 = __half22float2(*(const __half2*)&vv[u].x);
            float2 f1 = __half22float2(*(const __half2*)&vv[u].y);
            acc[0] += w * f0.x;
            acc[1] += w * f0.y;
            acc[2] += w * f1.x;
            acc[3] += w * f1.y;
        }
        if (half == 0) {
            int2 qa = qq[sel];
            attn_out[(size_t)qa.y * NUM_HEADS + hl] = swn[(qa.x >> 16) * 8 + hl];
        }
    }
    for (; i < deg; i++) {
        int2 q0 = g_csr2[off + i];
        uint2 v0 = __ldg(base + (size_t)(q0.x & 0xFFFF) * 64 + lcol);
        float w0 = swn[(q0.x >> 16) * 8 + h0];
        float2 f0 = __half22float2(*(const __half2*)&v0.x);
        float2 f1 = __half22float2(*(const __half2*)&v0.y);
        acc[0] += w0 * f0.x;
        acc[1] += w0 * f0.y;
        acc[2] += w0 * f1.x;
        acc[3] += w0 * f1.y;
        if (half == 0 && lane < 8)
            attn_out[(size_t)q0.y * NUM_HEADS + lane] = swn[(q0.x >> 16) * 8 + lane];
    }

    // lane writes its 4 cols: rst[d, half*128 + lane*4 ..]
    *(float4*)(rst + (size_t)d * HD + half * 128 + lane * 4) =
        make_float4(acc[0], acc[1], acc[2], acc[3]);
}

// ---------------- launch ---------------------------------------------------
extern "C" void kernel_launch(void* const* d_in, const int* in_sizes, int n_in,
                              void* d_out, int out_size) {
    const float* feat   = (const float*)d_in[0];   // [N, 256]
    const float* fc_w   = (const float*)d_in[1];   // [256, 256]
    const float* emb    = (const float*)d_in[2];   // [5, 8]
    const int*   e_feat = (const int*)d_in[3];     // [E]
    const int*   src    = (const int*)d_in[4];     // [E]
    const int*   dst    = (const int*)d_in[5];     // [E]

    float* out_rst  = (float*)d_out;                           // [N, 8, 32]
    float* out_attn = (float*)d_out + (size_t)N_NODES * HD;    // [E, 8]

    void* fs_ptr = nullptr;
    cudaGetSymbolAddress(&fs_ptr, g_feat_src);

    // 1) GEMM (tensor cores, tf32 single pass)
    {
        dim3 grid((N_NODES + 127) / 128, HD / 128);
        gemm_tf32_kernel<<<grid, 256>>>(feat, fc_w, (__half*)fs_ptr, N_NODES);
    }
    // 2) histogram (+ clears g_total)
    count_kernel<<<(N_EDGES + 255) / 256, 256>>>(dst, e_feat);
    // 3) fused offsets + softmax (+ re-zeroes g_cnt)
    offsets_softmax_kernel<<<(N_NODES + 255) / 256, 256>>>(emb);
    // 4) slim scatter to CSR
    scatter_csr_kernel<<<(N_EDGES + 255) / 256, 256>>>(src, dst, e_feat);
    // 5) aggregation + fused attn write (2 warps per node)
    agg_csr_kernel<<<(N_NODES + 3) / 4, 256>>>(out_rst, out_attn);
}

// round 9
// speedup vs baseline: 1.2422x; 1.2080x over previous
#include <cuda_runtime.h>
#include <cuda_bf16.h>
#include <cuda_fp16.h>
#include <math.h>
#include <stddef.h>
#include <stdint.h>

#define N_NODES 50000
#define N_EDGES 800000
#define IN_FEATS 256
#define HD 256          // NUM_HEADS * OUT_FEATS
#define NUM_HEADS 8
#define OUT_FEATS 32
#define NUM_ET 5

// ---------------- scratch (static device globals; no allocation) ----------
__device__ __half g_feat_src[(size_t)N_NODES * HD];         // 25.6 MB (fp16)
__device__ int    g_cnt[(size_t)N_NODES * NUM_ET];          // 1 MB (BSS zero)
__device__ float  g_w[(size_t)N_NODES * NUM_ET * NUM_HEADS];// 8 MB
__device__ int    g_off[N_NODES];
__device__ int    g_deg[N_NODES];
__device__ int    g_cur[N_NODES];
__device__ int2   g_csr2[N_EDGES];                          // {src|t<<16, e}
__device__ int    g_total;

// =====================================================================
// 1) GEMM: C[M,256](fp16) = A[M,256]*B[256,256]^T, single-pass tf32 MMA.
//    BM=128, BN=128, BK=32, 256 threads, 8 warps (4Mx2N), warp 32x64.
// =====================================================================
__device__ __forceinline__ void mma_tf32(float* c, const uint32_t* a,
                                         uint32_t b0, uint32_t b1) {
    asm volatile(
        "mma.sync.aligned.m16n8k8.row.col.f32.tf32.tf32.f32 "
        "{%0,%1,%2,%3},{%4,%5,%6,%7},{%8,%9},{%0,%1,%2,%3};\n"
        : "+f"(c[0]), "+f"(c[1]), "+f"(c[2]), "+f"(c[3])
        : "r"(a[0]), "r"(a[1]), "r"(a[2]), "r"(a[3]), "r"(b0), "r"(b1));
}

__device__ __forceinline__ float tf32r(float x) {
    float y;
    asm("cvt.rna.tf32.f32 %0, %1;" : "=f"(y) : "f"(x));
    return y;
}

__device__ __forceinline__ void cvt_store4(float* p, float4 v) {
    p[0] = tf32r(v.x);
    p[1] = tf32r(v.y);
    p[2] = tf32r(v.z);
    p[3] = tf32r(v.w);
}

__global__ __launch_bounds__(256) void gemm_tf32_kernel(
    const float* __restrict__ A, const float* __restrict__ B,
    __half* __restrict__ C, int M) {
    __shared__ float As[128][36];
    __shared__ float Bs[128][36];

    const int tid = threadIdx.x;
    const int m0 = blockIdx.x * 128;
    const int n0 = blockIdx.y * 128;
    const int warp = tid >> 5, lane = tid & 31;
    const int wm0 = (warp >> 1) * 32;
    const int wn0 = (warp & 1) * 64;
    const int g = lane >> 2, tg = lane & 3;

    const int row0 = tid >> 3;
    const int ac4 = (tid & 7) * 4;

    float acc[2][8][4];
#pragma unroll
    for (int i = 0; i < 2; i++)
#pragma unroll
        for (int j = 0; j < 8; j++)
#pragma unroll
            for (int q = 0; q < 4; q++) acc[i][j][q] = 0.f;

    float4 pa[4], pb[4];
#pragma unroll
    for (int r = 0; r < 4; r++) {
        int row = row0 + r * 32;
        pa[r] = make_float4(0.f, 0.f, 0.f, 0.f);
        if (m0 + row < M)
            pa[r] = __ldg((const float4*)(A + (size_t)(m0 + row) * 256 + ac4));
        pb[r] = __ldg((const float4*)(B + (size_t)(n0 + row) * 256 + ac4));
    }

#pragma unroll 1
    for (int k0 = 0; k0 < 256; k0 += 32) {
#pragma unroll
        for (int r = 0; r < 4; r++) {
            int row = row0 + r * 32;
            cvt_store4(&As[row][ac4], pa[r]);
            cvt_store4(&Bs[row][ac4], pb[r]);
        }
        __syncthreads();

        if (k0 + 32 < 256) {
            const int kn = k0 + 32;
#pragma unroll
            for (int r = 0; r < 4; r++) {
                int row = row0 + r * 32;
                if (m0 + row < M)
                    pa[r] = __ldg((const float4*)(A + (size_t)(m0 + row) * 256 + kn + ac4));
                pb[r] = __ldg((const float4*)(B + (size_t)(n0 + row) * 256 + kn + ac4));
            }
        }

#pragma unroll
        for (int kf = 0; kf < 4; kf++) {
            const int kk = kf * 8;
            uint32_t a[2][4], b[8][2];
#pragma unroll
            for (int i = 0; i < 2; i++) {
                int r0 = wm0 + i * 16 + g;
                a[i][0] = *(const uint32_t*)&As[r0][kk + tg];
                a[i][1] = *(const uint32_t*)&As[r0 + 8][kk + tg];
                a[i][2] = *(const uint32_t*)&As[r0][kk + tg + 4];
                a[i][3] = *(const uint32_t*)&As[r0 + 8][kk + tg + 4];
            }
#pragma unroll
            for (int j = 0; j < 8; j++) {
                int c0 = wn0 + j * 8 + g;
                b[j][0] = *(const uint32_t*)&Bs[c0][kk + tg];
                b[j][1] = *(const uint32_t*)&Bs[c0][kk + tg + 4];
            }
#pragma unroll
            for (int i = 0; i < 2; i++)
#pragma unroll
                for (int j = 0; j < 8; j++)
                    mma_tf32(acc[i][j], a[i], b[j][0], b[j][1]);
        }
        __syncthreads();
    }

#pragma unroll
    for (int i = 0; i < 2; i++)
#pragma unroll
        for (int j = 0; j < 8; j++) {
            int m_lo = m0 + wm0 + i * 16 + g;
            int col  = n0 + wn0 + j * 8 + tg * 2;
            if (m_lo < M)
                *(__half2*)(C + (size_t)m_lo * 256 + col) =
                    __floats2half2_rn(acc[i][j][0], acc[i][j][1]);
            if (m_lo + 8 < M)
                *(__half2*)(C + (size_t)(m_lo + 8) * 256 + col) =
                    __floats2half2_rn(acc[i][j][2], acc[i][j][3]);
        }
}

// ---------------- 2) histogram, 1 edge/thread (+ clear g_total) -----------
__global__ void count_kernel(const int* __restrict__ dst,
                             const int* __restrict__ ef) {
    int i = blockIdx.x * blockDim.x + threadIdx.x;
    if (i == 0) g_total = 0;
    if (i < N_EDGES)
        atomicAdd(&g_cnt[(size_t)dst[i] * NUM_ET + ef[i]], 1);
}

// ------- 3) fused CSR offsets + softmax (+ re-zero g_cnt for next run) ----
__global__ void offsets_softmax_kernel(const float* __restrict__ emb) {
    int n = blockIdx.x * blockDim.x + threadIdx.x;
    int lane = threadIdx.x & 31;

    int c[NUM_ET];
    int deg = 0;
    if (n < N_NODES) {
#pragma unroll
        for (int t = 0; t < NUM_ET; t++) {
            c[t] = g_cnt[(size_t)n * NUM_ET + t];
            deg += c[t];
        }
#pragma unroll
        for (int t = 0; t < NUM_ET; t++)
            g_cnt[(size_t)n * NUM_ET + t] = 0;   // restore for next replay
    }
    int incl = deg;
#pragma unroll
    for (int o = 1; o < 32; o <<= 1) {
        int v = __shfl_up_sync(0xffffffffu, incl, o);
        if (lane >= o) incl += v;
    }
    int total = __shfl_sync(0xffffffffu, incl, 31);
    int base = 0;
    if (lane == 0) base = atomicAdd(&g_total, total);
    base = __shfl_sync(0xffffffffu, base, 0);

    if (n < N_NODES) {
        int off = base + incl - deg;
        g_off[n] = off;
        g_cur[n] = off;
        g_deg[n] = deg;

#pragma unroll
        for (int h = 0; h < NUM_HEADS; h++) {
            float ev[NUM_ET];
            float m = -INFINITY;
#pragma unroll
            for (int t = 0; t < NUM_ET; t++) {
                ev[t] = __ldg(emb + t * NUM_HEADS + h);
                if (c[t] > 0) m = fmaxf(m, ev[t]);
            }
            float ex[NUM_ET];
            float denom = 0.f;
#pragma unroll
            for (int t = 0; t < NUM_ET; t++) {
                ex[t] = expf(ev[t] - m);
                denom += (float)c[t] * ex[t];
            }
            float inv = 1.f / denom;   // NaN only for deg==0 nodes (unread)
#pragma unroll
            for (int t = 0; t < NUM_ET; t++)
                g_w[((size_t)n * NUM_ET + t) * NUM_HEADS + h] = ex[t] * inv;
        }
    }
}

// ---------------- 4) scatter edges into CSR (slim), 1 edge/thread ---------
__global__ void scatter_csr_kernel(const int* __restrict__ src,
                                   const int* __restrict__ dst,
                                   const int* __restrict__ ef) {
    int e = blockIdx.x * blockDim.x + threadIdx.x;
    if (e >= N_EDGES) return;
    int s = src[e];
    int d = dst[e];
    int t = ef[e];
    int pos = atomicAdd(&g_cur[d], 1);
    g_csr2[pos] = make_int2(s | (t << 16), e);
}

// ---------------- 5) CSR aggregation + fused attn write (8-deep MLP) ------
__global__ __launch_bounds__(256) void agg_csr_kernel(float* __restrict__ rst,
                                                      float* __restrict__ attn_out) {
    __shared__ float sw[8][NUM_ET * NUM_HEADS];
    const int warp = threadIdx.x >> 5;
    const int lane = threadIdx.x & 31;
    const int d = blockIdx.x * 8 + warp;
    if (d >= N_NODES) return;

    sw[warp][lane] = g_w[(size_t)d * 40 + lane];
    if (lane < 8) sw[warp][32 + lane] = g_w[(size_t)d * 40 + 32 + lane];
    __syncwarp();

    const int off = g_off[d];
    const int deg = g_deg[d];
    const int h0 = lane >> 2;
    const int sel = lane >> 3;
    const int hl  = lane & 7;
    const uint4* base = (const uint4*)g_feat_src;

    float acc[8];
#pragma unroll
    for (int q = 0; q < 8; q++) acc[q] = 0.f;

    int i = 0;
    for (; i + 8 <= deg; i += 8) {
        int2 qq[8];
        uint4 vv[8];
        float ww[8];
#pragma unroll
        for (int u = 0; u < 8; u++) qq[u] = g_csr2[off + i + u];
#pragma unroll
        for (int u = 0; u < 8; u++)
            vv[u] = __ldg(base + (size_t)(qq[u].x & 0xFFFF) * 32 + lane);
#pragma unroll
        for (int u = 0; u < 8; u++) ww[u] = sw[warp][(qq[u].x >> 16) * 8 + h0];
#pragma unroll
        for (int u = 0; u < 8; u++) {
            const uint32_t* uv = &vv[u].x;
#pragma unroll
            for (int q = 0; q < 4; q++) {
                float2 f = __half22float2(*(const __half2*)&uv[q]);
                acc[q * 2]     += ww[u] * f.x;
                acc[q * 2 + 1] += ww[u] * f.y;
            }
        }
        {
            int2 qa = qq[sel];
            int2 qb = qq[sel + 4];
            attn_out[(size_t)qa.y * NUM_HEADS + hl] = sw[warp][(qa.x >> 16) * 8 + hl];
            attn_out[(size_t)qb.y * NUM_HEADS + hl] = sw[warp][(qb.x >> 16) * 8 + hl];
        }
    }
    for (; i + 4 <= deg; i += 4) {
        int2 qq[4];
        uint4 vv[4];
#pragma unroll
        for (int u = 0; u < 4; u++) qq[u] = g_csr2[off + i + u];
#pragma unroll
        for (int u = 0; u < 4; u++)
            vv[u] = __ldg(base + (size_t)(qq[u].x & 0xFFFF) * 32 + lane);
#pragma unroll
        for (int u = 0; u < 4; u++) {
            float w = sw[warp][(qq[u].x >> 16) * 8 + h0];
            const uint32_t* uv = &vv[u].x;
#pragma unroll
            for (int q = 0; q < 4; q++) {
                float2 f = __half22float2(*(const __half2*)&uv[q]);
                acc[q * 2]     += w * f.x;
                acc[q * 2 + 1] += w * f.y;
            }
        }
        int2 qa = qq[sel];
        attn_out[(size_t)qa.y * NUM_HEADS + hl] = sw[warp][(qa.x >> 16) * 8 + hl];
    }
    for (; i < deg; i++) {
        int2 q0 = g_csr2[off + i];
        uint4 v0 = __ldg(base + (size_t)(q0.x & 0xFFFF) * 32 + lane);
        float w0 = sw[warp][(q0.x >> 16) * 8 + h0];
        const uint32_t* u0 = &v0.x;
#pragma unroll
        for (int q = 0; q < 4; q++) {
            float2 f0 = __half22float2(*(const __half2*)&u0[q]);
            acc[q * 2]     += w0 * f0.x;
            acc[q * 2 + 1] += w0 * f0.y;
        }
        if (lane < 8)
            attn_out[(size_t)q0.y * NUM_HEADS + lane] = sw[warp][(q0.x >> 16) * 8 + lane];
    }

    float4* out = (float4*)(rst + (size_t)d * HD) + lane * 2;
    out[0] = make_float4(acc[0], acc[1], acc[2], acc[3]);
    out[1] = make_float4(acc[4], acc[5], acc[6], acc[7]);
}

// ---------------- launch ---------------------------------------------------
extern "C" void kernel_launch(void* const* d_in, const int* in_sizes, int n_in,
                              void* d_out, int out_size) {
    const float* feat   = (const float*)d_in[0];   // [N, 256]
    const float* fc_w   = (const float*)d_in[1];   // [256, 256]
    const float* emb    = (const float*)d_in[2];   // [5, 8]
    const int*   e_feat = (const int*)d_in[3];     // [E]
    const int*   src    = (const int*)d_in[4];     // [E]
    const int*   dst    = (const int*)d_in[5];     // [E]

    float* out_rst  = (float*)d_out;                           // [N, 8, 32]
    float* out_attn = (float*)d_out + (size_t)N_NODES * HD;    // [E, 8]

    // one-time host-side resources (created on the uncaptured correctness call)
    static cudaStream_t s2 = nullptr;
    static cudaEvent_t evFork = nullptr, evJoin = nullptr;
    if (!s2) {
        cudaStreamCreateWithFlags(&s2, cudaStreamNonBlocking);
        cudaEventCreateWithFlags(&evFork, cudaEventDisableTiming);
        cudaEventCreateWithFlags(&evJoin, cudaEventDisableTiming);
    }

    void* fs_ptr = nullptr;
    cudaGetSymbolAddress(&fs_ptr, g_feat_src);

    // fork: edge pipeline runs on side stream, concurrent with GEMM
    cudaEventRecord(evFork, 0);
    cudaStreamWaitEvent(s2, evFork, 0);

    // ---- main stream: GEMM (tensor cores, tf32 single pass) ----
    {
        dim3 grid((N_NODES + 127) / 128, HD / 128);
        gemm_tf32_kernel<<<grid, 256>>>(feat, fc_w, (__half*)fs_ptr, N_NODES);
    }

    // ---- side stream: edge pipeline ----
    count_kernel<<<(N_EDGES + 255) / 256, 256, 0, s2>>>(dst, e_feat);
    offsets_softmax_kernel<<<(N_NODES + 255) / 256, 256, 0, s2>>>(emb);
    scatter_csr_kernel<<<(N_EDGES + 255) / 256, 256, 0, s2>>>(src, dst, e_feat);

    // join
    cudaEventRecord(evJoin, s2);
    cudaStreamWaitEvent(0, evJoin, 0);

    // ---- main stream: aggregation + fused attn write ----
    agg_csr_kernel<<<(N_NODES + 7) / 8, 256>>>(out_rst, out_attn);
}